// round 3
// baseline (speedup 1.0000x reference)
#include <cuda_runtime.h>
#include <cstdint>
#include <cstddef>

#define N_NODES 20000
#define N_EDGES 200000
#define HID 128
#define NH 8
#define LAYERS 7
#define MLP_K 288      // padded K (285 -> 288, multiple of 16)
#define MLP_LD 320     // padded row stride / N (285 -> 320, multiple of 64)

// ---------------- scratch (static device globals; no runtime allocation) ----------------
__device__ float g_h[N_NODES * HID];
__device__ float g_x[N_NODES * HID];
__device__ float g_q[N_NODES * HID];
__device__ float g_k[N_NODES * HID];
__device__ float g_v[N_NODES * HID];
__device__ float g_attn[N_NODES * HID];
__device__ float g_tmp[N_NODES * HID];
__device__ float g_sc[N_EDGES * NH];
__device__ float g_m[N_NODES * NH];
__device__ float g_den[N_NODES * NH];
__device__ float g_y0[(size_t)N_EDGES * MLP_LD];
__device__ float g_y1[(size_t)N_EDGES * MLP_LD];
__device__ float g_Wpad[3 * MLP_K * MLP_LD];
__device__ float g_bpad[3 * MLP_LD];
__device__ float g_Wopad[MLP_K * 2];

// ---------------- helpers ----------------
__device__ __forceinline__ void atomicMaxF(float* addr, float val) {
    int* ia = (int*)addr;
    int old = *ia;
    while (__int_as_float(old) < val) {
        int assumed = old;
        old = atomicCAS(ia, assumed, __float_as_int(val));
        if (old == assumed) break;
    }
}

// ---------------- embedding: h = node_feats @ W_emb + b_emb ----------------
__global__ void embed_kernel(const float* __restrict__ nf, const float* __restrict__ We,
                             const float* __restrict__ be, float* __restrict__ h) {
    int idx = blockIdx.x * blockDim.x + threadIdx.x;
    if (idx >= N_NODES * HID) return;
    int n = idx >> 7, c = idx & 127;
    h[idx] = fmaf(nf[n * 2 + 0], We[c], fmaf(nf[n * 2 + 1], We[HID + c], be[c]));
}

// ---------------- LayerNorm: warp per node ----------------
__global__ void ln_kernel(const float* __restrict__ h, const float* __restrict__ g,
                          const float* __restrict__ b, float* __restrict__ x) {
    int node = (blockIdx.x * blockDim.x + threadIdx.x) >> 5;
    int lane = threadIdx.x & 31;
    if (node >= N_NODES) return;
    float4 v = *(const float4*)&h[node * HID + lane * 4];
    float s = v.x + v.y + v.z + v.w;
    #pragma unroll
    for (int o = 16; o; o >>= 1) s += __shfl_xor_sync(0xffffffffu, s, o);
    float mu = s * (1.0f / 128.0f);
    float dx = v.x - mu, dy = v.y - mu, dz = v.z - mu, dw = v.w - mu;
    float q = dx * dx + dy * dy + dz * dz + dw * dw;
    #pragma unroll
    for (int o = 16; o; o >>= 1) q += __shfl_xor_sync(0xffffffffu, q, o);
    float rs = rsqrtf(q * (1.0f / 128.0f) + 1e-5f);
    float4 gv = *(const float4*)&g[lane * 4];
    float4 bv = *(const float4*)&b[lane * 4];
    float4 o4;
    o4.x = fmaf(dx * rs, gv.x, bv.x);
    o4.y = fmaf(dy * rs, gv.y, bv.y);
    o4.z = fmaf(dz * rs, gv.z, bv.z);
    o4.w = fmaf(dw * rs, gv.w, bv.w);
    *(float4*)&x[node * HID + lane * 4] = o4;
}

// ---------------- tiled fp32 GEMM: C = act(A@W + bias [+ res]) ----------------
// A[M,K] (row stride ldA), W[K,N] row-major (stride N), C[M,N] (stride N).
// Requires: N % 64 == 0, K % 16 == 0.
#define BM 128
#define BN 64
#define BK 16
#define TM 8
#define TN 4

__global__ __launch_bounds__(256)
void gemm_kernel(const float* __restrict__ A, const float* __restrict__ W,
                 const float* __restrict__ bias, const float* __restrict__ res,
                 float* __restrict__ C, int M, int K, int ldA, int N, int relu) {
    __shared__ float As[BK][BM + 4];
    __shared__ float Bs[BK][BN];
    int tid = threadIdx.x;
    int tx = tid & 15;       // col group (0..15) -> 4 cols each
    int ty = tid >> 4;       // row group (0..15) -> 8 rows each
    int rowBase = blockIdx.y * BM;
    int colBase = blockIdx.x * BN;

    float acc[TM][TN];
    #pragma unroll
    for (int i = 0; i < TM; i++)
        #pragma unroll
        for (int j = 0; j < TN; j++) acc[i][j] = 0.0f;

    for (int k0 = 0; k0 < K; k0 += BK) {
        // A tile 128x16 -> As[k][m] (transposed)
        #pragma unroll
        for (int it = 0; it < 2; it++) {
            int i4 = tid + it * 256;      // 0..511
            int r = i4 >> 2;              // 0..127
            int c4 = (i4 & 3) * 4;        // 0,4,8,12
            int gr = rowBase + r;
            float4 v = make_float4(0.f, 0.f, 0.f, 0.f);
            if (gr < M) v = *(const float4*)&A[(size_t)gr * ldA + k0 + c4];
            As[c4 + 0][r] = v.x; As[c4 + 1][r] = v.y;
            As[c4 + 2][r] = v.z; As[c4 + 3][r] = v.w;
        }
        // B tile 16x64
        {
            int r = tid >> 4;             // 0..15
            int c4 = (tid & 15) * 4;
            float4 v = *(const float4*)&W[(size_t)(k0 + r) * N + colBase + c4];
            *(float4*)&Bs[r][c4] = v;
        }
        __syncthreads();
        #pragma unroll
        for (int kk = 0; kk < BK; kk++) {
            float4 a0 = *(const float4*)&As[kk][ty * TM];
            float4 a1 = *(const float4*)&As[kk][ty * TM + 4];
            float4 b0 = *(const float4*)&Bs[kk][tx * TN];
            float a[TM] = {a0.x, a0.y, a0.z, a0.w, a1.x, a1.y, a1.z, a1.w};
            float b[TN] = {b0.x, b0.y, b0.z, b0.w};
            #pragma unroll
            for (int i = 0; i < TM; i++)
                #pragma unroll
                for (int j = 0; j < TN; j++)
                    acc[i][j] = fmaf(a[i], b[j], acc[i][j]);
        }
        __syncthreads();
    }

    int gc = colBase + tx * TN;
    float4 bv = *(const float4*)&bias[gc];
    #pragma unroll
    for (int i = 0; i < TM; i++) {
        int gr = rowBase + ty * TM + i;
        if (gr >= M) continue;
        float4 o;
        o.x = acc[i][0] + bv.x; o.y = acc[i][1] + bv.y;
        o.z = acc[i][2] + bv.z; o.w = acc[i][3] + bv.w;
        if (res) {
            float4 rv = *(const float4*)&res[(size_t)gr * N + gc];
            o.x += rv.x; o.y += rv.y; o.z += rv.z; o.w += rv.w;
        }
        if (relu) {
            o.x = fmaxf(o.x, 0.f); o.y = fmaxf(o.y, 0.f);
            o.z = fmaxf(o.z, 0.f); o.w = fmaxf(o.w, 0.f);
        }
        *(float4*)&C[(size_t)gr * N + gc] = o;
    }
}

// ---------------- attention ----------------
__global__ void init_attn_kernel(float* __restrict__ m, float* __restrict__ den,
                                 float* __restrict__ attn) {
    int idx = blockIdx.x * blockDim.x + threadIdx.x;
    if (idx < N_NODES * NH) { m[idx] = __int_as_float(0xFF800000); den[idx] = 0.0f; }
    if (idx < N_NODES * HID) attn[idx] = 0.0f;
}

// warp per edge: scores[e,h] = dot(Q[dst],K[src]) per head / 4; atomicMax into m[dst]
__global__ void score_kernel(const float* __restrict__ q, const float* __restrict__ k,
                             const int* __restrict__ src, const int* __restrict__ dst,
                             float* __restrict__ scores, float* __restrict__ m) {
    int e = (blockIdx.x * blockDim.x + threadIdx.x) >> 5;
    int lane = threadIdx.x & 31;
    if (e >= N_EDGES) return;
    int s = src[e], d = dst[e];
    float4 qv = *(const float4*)&q[(size_t)d * HID + lane * 4];
    float4 kv = *(const float4*)&k[(size_t)s * HID + lane * 4];
    float p = qv.x * kv.x + qv.y * kv.y + qv.z * kv.z + qv.w * kv.w;
    p += __shfl_xor_sync(0xffffffffu, p, 1);
    p += __shfl_xor_sync(0xffffffffu, p, 2);
    if ((lane & 3) == 0) {
        int hh = lane >> 2;
        float sc = p * 0.25f;              // / sqrt(DH=16)
        scores[e * NH + hh] = sc;
        atomicMaxF(&m[d * NH + hh], sc);
    }
}

// thread per (e,h): ex = exp(sc - m[dst]); scores <- ex; den[dst] += ex
__global__ void expsum_kernel(float* __restrict__ scores, const float* __restrict__ m,
                              float* __restrict__ den, const int* __restrict__ dst) {
    int idx = blockIdx.x * blockDim.x + threadIdx.x;
    if (idx >= N_EDGES * NH) return;
    int e = idx >> 3, hh = idx & 7;
    int d = dst[e];
    float ex = __expf(scores[idx] - m[d * NH + hh]);
    scores[idx] = ex;
    atomicAdd(&den[d * NH + hh], ex);
}

// warp per edge: attn[dst] += (ex/den[dst]) * V[src]
__global__ void agg_kernel(const float* __restrict__ scores, const float* __restrict__ den,
                           const float* __restrict__ v, const int* __restrict__ src,
                           const int* __restrict__ dst, float* __restrict__ attn) {
    int e = (blockIdx.x * blockDim.x + threadIdx.x) >> 5;
    int lane = threadIdx.x & 31;
    if (e >= N_EDGES) return;
    int s = src[e], d = dst[e];
    int hh = lane >> 2;
    float w = scores[e * NH + hh] / den[d * NH + hh];
    float4 vv = *(const float4*)&v[(size_t)s * HID + lane * 4];
    float* dst_ptr = &attn[(size_t)d * HID + lane * 4];
    atomicAdd(dst_ptr + 0, w * vv.x);
    atomicAdd(dst_ptr + 1, w * vv.y);
    atomicAdd(dst_ptr + 2, w * vv.z);
    atomicAdd(dst_ptr + 3, w * vv.w);
}

// ---------------- classifier prep ----------------
__global__ void padW_kernel(const float* __restrict__ Wh, float* __restrict__ Wpad) {
    int idx = blockIdx.x * blockDim.x + threadIdx.x;
    if (idx >= 3 * MLP_K * MLP_LD) return;
    int i = idx / (MLP_K * MLP_LD);
    int rem = idx - i * (MLP_K * MLP_LD);
    int r = rem / MLP_LD, c = rem - r * MLP_LD;
    Wpad[idx] = (r < 285 && c < 285) ? Wh[i * 285 * 285 + r * 285 + c] : 0.0f;
}

__global__ void padb_kernel(const float* __restrict__ bh, float* __restrict__ bpad,
                            const float* __restrict__ Wo, float* __restrict__ Wopad) {
    int idx = blockIdx.x * blockDim.x + threadIdx.x;
    if (idx < 3 * MLP_LD) {
        int i = idx / MLP_LD, c = idx - i * MLP_LD;
        bpad[idx] = (c < 285) ? bh[i * 285 + c] : 0.0f;
    }
    if (idx < MLP_K * 2) {
        int r = idx >> 1;
        Wopad[idx] = (r < 285) ? Wo[idx] : 0.0f;
    }
}

// build y0[e, 0:320] = [h[src](128) | h[dst](128) | curr_emb[pc](8) | curr_emb[rc](8)
//                      | pay_emb[pf](8) | numericals(5) | zeros(35)]
__global__ void gather_kernel(const float* __restrict__ h, const float* __restrict__ ce,
                              const float* __restrict__ pe, const float* __restrict__ num,
                              const int* __restrict__ src, const int* __restrict__ dst,
                              const int* __restrict__ pc, const int* __restrict__ rc,
                              const int* __restrict__ pf, float* __restrict__ y) {
    size_t idx = (size_t)blockIdx.x * blockDim.x + threadIdx.x;
    if (idx >= (size_t)N_EDGES * MLP_LD) return;
    int e = (int)(idx / MLP_LD);
    int c = (int)(idx - (size_t)e * MLP_LD);
    float val;
    if (c < 128)       val = h[(size_t)src[e] * HID + c];
    else if (c < 256)  val = h[(size_t)dst[e] * HID + (c - 128)];
    else if (c < 264)  val = ce[pc[e] * 8 + (c - 256)];
    else if (c < 272)  val = ce[rc[e] * 8 + (c - 264)];
    else if (c < 280)  val = pe[pf[e] * 8 + (c - 272)];
    else if (c < 285)  val = num[(size_t)e * 5 + (c - 280)];
    else               val = 0.0f;
    y[idx] = val;
}

// ---------------- final projection: out[E,2] = y @ Wo + bo (warp per edge) ----------------
__global__ void out_kernel(const float* __restrict__ y, const float* __restrict__ Wo,
                           const float* __restrict__ bo, float* __restrict__ out) {
    __shared__ float Ws[MLP_K * 2];
    int tid = threadIdx.x;
    for (int i = tid; i < MLP_K * 2; i += blockDim.x) Ws[i] = Wo[i];
    __syncthreads();
    int e = (blockIdx.x * blockDim.x + tid) >> 5;
    int lane = tid & 31;
    if (e >= N_EDGES) return;
    const float* yr = &y[(size_t)e * MLP_LD];
    float a0 = 0.f, a1 = 0.f;
    #pragma unroll
    for (int kk = lane; kk < MLP_K; kk += 32) {
        float yv = yr[kk];
        a0 = fmaf(yv, Ws[kk * 2 + 0], a0);
        a1 = fmaf(yv, Ws[kk * 2 + 1], a1);
    }
    #pragma unroll
    for (int o = 16; o; o >>= 1) {
        a0 += __shfl_xor_sync(0xffffffffu, a0, o);
        a1 += __shfl_xor_sync(0xffffffffu, a1, o);
    }
    if (lane == 0) {
        out[e * 2 + 0] = a0 + bo[0];
        out[e * 2 + 1] = a1 + bo[1];
    }
}

// ---------------- host ----------------
static inline int G(long long n) { return (int)((n + 255) / 256); }

extern "C" void kernel_launch(void* const* d_in, const int* in_sizes, int n_in,
                              void* d_out, int out_size) {
    const float* node_feats = (const float*)d_in[0];
    const float* numericals = (const float*)d_in[1];
    const float* W_emb = (const float*)d_in[2];
    const float* b_emb = (const float*)d_in[3];
    const float* WQ = (const float*)d_in[4];
    const float* bQ = (const float*)d_in[5];
    const float* WK = (const float*)d_in[6];
    const float* bK = (const float*)d_in[7];
    const float* WV = (const float*)d_in[8];
    const float* bV = (const float*)d_in[9];
    const float* WO = (const float*)d_in[10];
    const float* bO = (const float*)d_in[11];
    const float* ln1_g = (const float*)d_in[12];
    const float* ln1_b = (const float*)d_in[13];
    const float* ln2_g = (const float*)d_in[14];
    const float* ln2_b = (const float*)d_in[15];
    const float* W1 = (const float*)d_in[16];
    const float* b1 = (const float*)d_in[17];
    const float* W2 = (const float*)d_in[18];
    const float* b2 = (const float*)d_in[19];
    const float* curr_emb = (const float*)d_in[20];
    const float* pay_emb = (const float*)d_in[21];
    const float* mlp_Wh = (const float*)d_in[22];
    const float* mlp_bh = (const float*)d_in[23];
    const float* mlp_Wo = (const float*)d_in[24];
    const float* mlp_bo = (const float*)d_in[25];
    const int* src = (const int*)d_in[26];
    const int* dst = (const int*)d_in[27];
    const int* pc = (const int*)d_in[28];
    const int* rc = (const int*)d_in[29];
    const int* pf = (const int*)d_in[30];
    float* out = (float*)d_out;

    float *h, *x, *q, *k, *v, *attn, *tmp, *sc, *m, *den, *y0, *y1, *Wpad, *bpad, *Wopad;
    cudaGetSymbolAddress((void**)&h, g_h);
    cudaGetSymbolAddress((void**)&x, g_x);
    cudaGetSymbolAddress((void**)&q, g_q);
    cudaGetSymbolAddress((void**)&k, g_k);
    cudaGetSymbolAddress((void**)&v, g_v);
    cudaGetSymbolAddress((void**)&attn, g_attn);
    cudaGetSymbolAddress((void**)&tmp, g_tmp);
    cudaGetSymbolAddress((void**)&sc, g_sc);
    cudaGetSymbolAddress((void**)&m, g_m);
    cudaGetSymbolAddress((void**)&den, g_den);
    cudaGetSymbolAddress((void**)&y0, g_y0);
    cudaGetSymbolAddress((void**)&y1, g_y1);
    cudaGetSymbolAddress((void**)&Wpad, g_Wpad);
    cudaGetSymbolAddress((void**)&bpad, g_bpad);
    cudaGetSymbolAddress((void**)&Wopad, g_Wopad);

    // classifier weight padding (independent of the layer loop)
    padW_kernel<<<G(3 * MLP_K * MLP_LD), 256>>>(mlp_Wh, Wpad);
    padb_kernel<<<G(3 * MLP_LD), 256>>>(mlp_bh, bpad, mlp_Wo, Wopad);

    // node embedding
    embed_kernel<<<G((long long)N_NODES * HID), 256>>>(node_feats, W_emb, b_emb, h);

    auto gemm = [&](const float* A, const float* W, const float* bias, const float* res,
                    float* C, int M, int K, int ldA, int Ncols, int relu) {
        dim3 grid(Ncols / BN, (M + BM - 1) / BM);
        gemm_kernel<<<grid, 256>>>(A, W, bias, res, C, M, K, ldA, Ncols, relu);
    };

    for (int l = 0; l < LAYERS; l++) {
        const int WOFF = l * HID * HID, BOFF = l * HID;
        // attention block
        ln_kernel<<<G((long long)N_NODES * 32), 256>>>(h, ln1_g + BOFF, ln1_b + BOFF, x);
        gemm(x, WQ + WOFF, bQ + BOFF, nullptr, q, N_NODES, HID, HID, HID, 0);
        gemm(x, WK + WOFF, bK + BOFF, nullptr, k, N_NODES, HID, HID, HID, 0);
        gemm(x, WV + WOFF, bV + BOFF, nullptr, v, N_NODES, HID, HID, HID, 0);
        init_attn_kernel<<<G((long long)N_NODES * HID), 256>>>(m, den, attn);
        score_kernel<<<G((long long)N_EDGES * 32), 256>>>(q, k, src, dst, sc, m);
        expsum_kernel<<<G((long long)N_EDGES * NH), 256>>>(sc, m, den, dst);
        agg_kernel<<<G((long long)N_EDGES * 32), 256>>>(sc, den, v, src, dst, attn);
        gemm(attn, WO + WOFF, bO + BOFF, h, h, N_NODES, HID, HID, HID, 0);
        // FFN block
        ln_kernel<<<G((long long)N_NODES * 32), 256>>>(h, ln2_g + BOFF, ln2_b + BOFF, x);
        gemm(x, W1 + WOFF, b1 + BOFF, nullptr, tmp, N_NODES, HID, HID, HID, 1);
        gemm(tmp, W2 + WOFF, b2 + BOFF, h, h, N_NODES, HID, HID, HID, 0);
    }

    // edge classifier
    gather_kernel<<<G((long long)N_EDGES * MLP_LD), 256>>>(
        h, curr_emb, pay_emb, numericals, src, dst, pc, rc, pf, y0);
    gemm(y0, Wpad + 0 * MLP_K * MLP_LD, bpad + 0 * MLP_LD, nullptr, y1,
         N_EDGES, MLP_K, MLP_LD, MLP_LD, 1);
    gemm(y1, Wpad + 1 * MLP_K * MLP_LD, bpad + 1 * MLP_LD, nullptr, y0,
         N_EDGES, MLP_K, MLP_LD, MLP_LD, 1);
    gemm(y0, Wpad + 2 * MLP_K * MLP_LD, bpad + 2 * MLP_LD, nullptr, y1,
         N_EDGES, MLP_K, MLP_LD, MLP_LD, 1);
    out_kernel<<<G((long long)N_EDGES * 32), 256>>>(y1, Wopad, mlp_bo, out);
}

// round 4
// speedup vs baseline: 1.2309x; 1.2309x over previous
#include <cuda_runtime.h>
#include <cstdint>
#include <cstddef>

#define N_NODES 20000
#define N_EDGES 200000
#define HID 128
#define NH 8
#define LAYERS 7
#define MLP_K 288      // padded K (285 -> 288, multiple of 16)
#define MLP_LD 320     // padded row stride / N (285 -> 320, multiple of 64)

// ---------------- scratch (static device globals; no runtime allocation) ----------------
__device__ float g_h[N_NODES * HID];
__device__ float g_x[N_NODES * HID];
__device__ float g_q[N_NODES * HID];
__device__ float g_k[N_NODES * HID];
__device__ float g_v[N_NODES * HID];
__device__ float g_attn[N_NODES * HID];
__device__ float g_tmp[N_NODES * HID];
__device__ float g_sc[N_EDGES * NH];
__device__ float g_m[N_NODES * NH];
__device__ float g_den[N_NODES * NH];
__device__ float g_y0[(size_t)N_EDGES * MLP_LD];
__device__ float g_y1[(size_t)N_EDGES * MLP_LD];
__device__ float g_Wpad[3 * MLP_K * MLP_LD];
__device__ float g_bpad[3 * MLP_LD];
__device__ float g_Wopad[MLP_K * 2];

// ---------------- helpers ----------------
__device__ __forceinline__ void atomicMaxF(float* addr, float val) {
    int* ia = (int*)addr;
    int old = *ia;
    while (__int_as_float(old) < val) {
        int assumed = old;
        old = atomicCAS(ia, assumed, __float_as_int(val));
        if (old == assumed) break;
    }
}

__device__ __forceinline__ float tf32r(float x) {
    unsigned u;
    asm("cvt.rna.tf32.f32 %0, %1;" : "=r"(u) : "f"(x));
    return __uint_as_float(u);
}

// ---------------- embedding: h = node_feats @ W_emb + b_emb ----------------
__global__ void embed_kernel(const float* __restrict__ nf, const float* __restrict__ We,
                             const float* __restrict__ be, float* __restrict__ h) {
    int idx = blockIdx.x * blockDim.x + threadIdx.x;
    if (idx >= N_NODES * HID) return;
    int n = idx >> 7, c = idx & 127;
    h[idx] = fmaf(nf[n * 2 + 0], We[c], fmaf(nf[n * 2 + 1], We[HID + c], be[c]));
}

// ---------------- LayerNorm: warp per node ----------------
__global__ void ln_kernel(const float* __restrict__ h, const float* __restrict__ g,
                          const float* __restrict__ b, float* __restrict__ x) {
    int node = (blockIdx.x * blockDim.x + threadIdx.x) >> 5;
    int lane = threadIdx.x & 31;
    if (node >= N_NODES) return;
    float4 v = *(const float4*)&h[node * HID + lane * 4];
    float s = v.x + v.y + v.z + v.w;
    #pragma unroll
    for (int o = 16; o; o >>= 1) s += __shfl_xor_sync(0xffffffffu, s, o);
    float mu = s * (1.0f / 128.0f);
    float dx = v.x - mu, dy = v.y - mu, dz = v.z - mu, dw = v.w - mu;
    float q = dx * dx + dy * dy + dz * dz + dw * dw;
    #pragma unroll
    for (int o = 16; o; o >>= 1) q += __shfl_xor_sync(0xffffffffu, q, o);
    float rs = rsqrtf(q * (1.0f / 128.0f) + 1e-5f);
    float4 gv = *(const float4*)&g[lane * 4];
    float4 bv = *(const float4*)&b[lane * 4];
    float4 o4;
    o4.x = fmaf(dx * rs, gv.x, bv.x);
    o4.y = fmaf(dy * rs, gv.y, bv.y);
    o4.z = fmaf(dz * rs, gv.z, bv.z);
    o4.w = fmaf(dw * rs, gv.w, bv.w);
    *(float4*)&x[node * HID + lane * 4] = o4;
}

// ---------------- tiled fp32 GEMM (node pipeline): C = act(A@W + bias [+ res]) ------
#define BM 128
#define BN 64
#define BK 16
#define TM 8
#define TN 4

__global__ __launch_bounds__(256)
void gemm_kernel(const float* __restrict__ A, const float* __restrict__ W,
                 const float* __restrict__ bias, const float* __restrict__ res,
                 float* __restrict__ C, int M, int K, int ldA, int N, int relu) {
    __shared__ float As[BK][BM + 4];
    __shared__ float Bs[BK][BN];
    int tid = threadIdx.x;
    int tx = tid & 15;
    int ty = tid >> 4;
    int rowBase = blockIdx.y * BM;
    int colBase = blockIdx.x * BN;

    float acc[TM][TN];
    #pragma unroll
    for (int i = 0; i < TM; i++)
        #pragma unroll
        for (int j = 0; j < TN; j++) acc[i][j] = 0.0f;

    for (int k0 = 0; k0 < K; k0 += BK) {
        #pragma unroll
        for (int it = 0; it < 2; it++) {
            int i4 = tid + it * 256;
            int r = i4 >> 2;
            int c4 = (i4 & 3) * 4;
            int gr = rowBase + r;
            float4 v = make_float4(0.f, 0.f, 0.f, 0.f);
            if (gr < M) v = *(const float4*)&A[(size_t)gr * ldA + k0 + c4];
            As[c4 + 0][r] = v.x; As[c4 + 1][r] = v.y;
            As[c4 + 2][r] = v.z; As[c4 + 3][r] = v.w;
        }
        {
            int r = tid >> 4;
            int c4 = (tid & 15) * 4;
            float4 v = *(const float4*)&W[(size_t)(k0 + r) * N + colBase + c4];
            *(float4*)&Bs[r][c4] = v;
        }
        __syncthreads();
        #pragma unroll
        for (int kk = 0; kk < BK; kk++) {
            float4 a0 = *(const float4*)&As[kk][ty * TM];
            float4 a1 = *(const float4*)&As[kk][ty * TM + 4];
            float4 b0 = *(const float4*)&Bs[kk][tx * TN];
            float a[TM] = {a0.x, a0.y, a0.z, a0.w, a1.x, a1.y, a1.z, a1.w};
            float b[TN] = {b0.x, b0.y, b0.z, b0.w};
            #pragma unroll
            for (int i = 0; i < TM; i++)
                #pragma unroll
                for (int j = 0; j < TN; j++)
                    acc[i][j] = fmaf(a[i], b[j], acc[i][j]);
        }
        __syncthreads();
    }

    int gc = colBase + tx * TN;
    float4 bv = *(const float4*)&bias[gc];
    #pragma unroll
    for (int i = 0; i < TM; i++) {
        int gr = rowBase + ty * TM + i;
        if (gr >= M) continue;
        float4 o;
        o.x = acc[i][0] + bv.x; o.y = acc[i][1] + bv.y;
        o.z = acc[i][2] + bv.z; o.w = acc[i][3] + bv.w;
        if (res) {
            float4 rv = *(const float4*)&res[(size_t)gr * N + gc];
            o.x += rv.x; o.y += rv.y; o.z += rv.z; o.w += rv.w;
        }
        if (relu) {
            o.x = fmaxf(o.x, 0.f); o.y = fmaxf(o.y, 0.f);
            o.z = fmaxf(o.z, 0.f); o.w = fmaxf(o.w, 0.f);
        }
        *(float4*)&C[(size_t)gr * N + gc] = o;
    }
}

// ---------------- tf32 tensor-core GEMM for edge MLP ----------------
// C[M, 320] = relu(A[M, 320(K=288)] @ W[288, 320] + bias)
// Block: 128 threads (4 warps, 2x2), block tile 128x64, warp tile 64x32.
#define GK 288
#define GN 320
#define ASTRIDE 20   // 16 + 4 pad: conflict-free for m16n8k8 A-fragment reads
#define BSTRIDE 72   // 64 + 8 pad: conflict-free for B-fragment reads

__global__ __launch_bounds__(128)
void mma_gemm_kernel(const float* __restrict__ A, const float* __restrict__ W,
                     const float* __restrict__ bias, float* __restrict__ C, int M) {
    __shared__ float As[2][128][ASTRIDE];
    __shared__ float Bs[2][16][BSTRIDE];

    int tid = threadIdx.x;
    int lane = tid & 31, warp = tid >> 5;
    int warpM = warp & 1, warpN = warp >> 1;   // 2 x 2 warps
    int rowBase = blockIdx.y * 128;
    int colBase = blockIdx.x * 64;
    int gq = lane >> 2, tg = lane & 3;

    float acc[4][4][4];
    #pragma unroll
    for (int mi = 0; mi < 4; mi++)
        #pragma unroll
        for (int ni = 0; ni < 4; ni++)
            #pragma unroll
            for (int r = 0; r < 4; r++) acc[mi][ni][r] = 0.0f;

    // A staging: one row per thread (128 rows), 16 floats per chunk
    int aRow = rowBase + tid;
    bool aValid = aRow < M;
    const float* aPtr = A + (size_t)aRow * GN;
    // B staging: 16 rows x 64 cols; thread -> (row = tid/8, col8 = (tid%8)*8)
    int bRow = tid >> 3;
    int bCol = (tid & 7) * 8;
    const float* bPtr = W + (size_t)bRow * GN + colBase + bCol;

    float4 ra[4], rb[2];

    // prologue: chunk 0
    #pragma unroll
    for (int t = 0; t < 4; t++)
        ra[t] = aValid ? *(const float4*)(aPtr + t * 4) : make_float4(0.f, 0.f, 0.f, 0.f);
    rb[0] = *(const float4*)(bPtr);
    rb[1] = *(const float4*)(bPtr + 4);

    #pragma unroll
    for (int t = 0; t < 4; t++) {
        As[0][tid][t * 4 + 0] = tf32r(ra[t].x);
        As[0][tid][t * 4 + 1] = tf32r(ra[t].y);
        As[0][tid][t * 4 + 2] = tf32r(ra[t].z);
        As[0][tid][t * 4 + 3] = tf32r(ra[t].w);
    }
    Bs[0][bRow][bCol + 0] = tf32r(rb[0].x); Bs[0][bRow][bCol + 1] = tf32r(rb[0].y);
    Bs[0][bRow][bCol + 2] = tf32r(rb[0].z); Bs[0][bRow][bCol + 3] = tf32r(rb[0].w);
    Bs[0][bRow][bCol + 4] = tf32r(rb[1].x); Bs[0][bRow][bCol + 5] = tf32r(rb[1].y);
    Bs[0][bRow][bCol + 6] = tf32r(rb[1].z); Bs[0][bRow][bCol + 7] = tf32r(rb[1].w);
    __syncthreads();

    const int NCHUNK = GK / 16;   // 18
    #pragma unroll 1
    for (int c = 0; c < NCHUNK; c++) {
        int cur = c & 1;
        if (c < NCHUNK - 1) {
            int k0 = (c + 1) * 16;
            #pragma unroll
            for (int t = 0; t < 4; t++)
                ra[t] = aValid ? *(const float4*)(aPtr + k0 + t * 4)
                               : make_float4(0.f, 0.f, 0.f, 0.f);
            rb[0] = *(const float4*)(bPtr + (size_t)k0 * GN);
            rb[1] = *(const float4*)(bPtr + (size_t)k0 * GN + 4);
        }

        // compute chunk 'cur': two k=8 steps
        #pragma unroll
        for (int kk = 0; kk < 16; kk += 8) {
            unsigned af[4][4];
            #pragma unroll
            for (int mi = 0; mi < 4; mi++) {
                int r = warpM * 64 + mi * 16 + gq;
                int cc = kk + tg;
                af[mi][0] = __float_as_uint(As[cur][r][cc]);
                af[mi][1] = __float_as_uint(As[cur][r + 8][cc]);
                af[mi][2] = __float_as_uint(As[cur][r][cc + 4]);
                af[mi][3] = __float_as_uint(As[cur][r + 8][cc + 4]);
            }
            #pragma unroll
            for (int ni = 0; ni < 4; ni++) {
                int bc = warpN * 32 + ni * 8 + gq;
                unsigned b0 = __float_as_uint(Bs[cur][kk + tg][bc]);
                unsigned b1 = __float_as_uint(Bs[cur][kk + tg + 4][bc]);
                #pragma unroll
                for (int mi = 0; mi < 4; mi++) {
                    asm volatile(
                        "mma.sync.aligned.m16n8k8.row.col.f32.tf32.tf32.f32 "
                        "{%0,%1,%2,%3},{%4,%5,%6,%7},{%8,%9},{%0,%1,%2,%3};"
                        : "+f"(acc[mi][ni][0]), "+f"(acc[mi][ni][1]),
                          "+f"(acc[mi][ni][2]), "+f"(acc[mi][ni][3])
                        : "r"(af[mi][0]), "r"(af[mi][1]), "r"(af[mi][2]), "r"(af[mi][3]),
                          "r"(b0), "r"(b1));
                }
            }
        }

        if (c < NCHUNK - 1) {
            int nxt = cur ^ 1;
            #pragma unroll
            for (int t = 0; t < 4; t++) {
                As[nxt][tid][t * 4 + 0] = tf32r(ra[t].x);
                As[nxt][tid][t * 4 + 1] = tf32r(ra[t].y);
                As[nxt][tid][t * 4 + 2] = tf32r(ra[t].z);
                As[nxt][tid][t * 4 + 3] = tf32r(ra[t].w);
            }
            Bs[nxt][bRow][bCol + 0] = tf32r(rb[0].x); Bs[nxt][bRow][bCol + 1] = tf32r(rb[0].y);
            Bs[nxt][bRow][bCol + 2] = tf32r(rb[0].z); Bs[nxt][bRow][bCol + 3] = tf32r(rb[0].w);
            Bs[nxt][bRow][bCol + 4] = tf32r(rb[1].x); Bs[nxt][bRow][bCol + 5] = tf32r(rb[1].y);
            Bs[nxt][bRow][bCol + 6] = tf32r(rb[1].z); Bs[nxt][bRow][bCol + 7] = tf32r(rb[1].w);
            __syncthreads();
        }
    }

    // epilogue: bias + relu, float2 stores
    #pragma unroll
    for (int ni = 0; ni < 4; ni++) {
        int gc = colBase + warpN * 32 + ni * 8 + 2 * tg;
        float2 bv = *(const float2*)&bias[gc];
        #pragma unroll
        for (int mi = 0; mi < 4; mi++) {
            int r0 = rowBase + warpM * 64 + mi * 16 + gq;
            if (r0 < M) {
                float2 o;
                o.x = fmaxf(acc[mi][ni][0] + bv.x, 0.f);
                o.y = fmaxf(acc[mi][ni][1] + bv.y, 0.f);
                *(float2*)&C[(size_t)r0 * GN + gc] = o;
            }
            int r1 = r0 + 8;
            if (r1 < M) {
                float2 o;
                o.x = fmaxf(acc[mi][ni][2] + bv.x, 0.f);
                o.y = fmaxf(acc[mi][ni][3] + bv.y, 0.f);
                *(float2*)&C[(size_t)r1 * GN + gc] = o;
            }
        }
    }
}

// ---------------- attention ----------------
__global__ void init_attn_kernel(float* __restrict__ m, float* __restrict__ den,
                                 float* __restrict__ attn) {
    int idx = blockIdx.x * blockDim.x + threadIdx.x;
    if (idx < N_NODES * NH) { m[idx] = __int_as_float(0xFF800000); den[idx] = 0.0f; }
    if (idx < N_NODES * HID) attn[idx] = 0.0f;
}

__global__ void score_kernel(const float* __restrict__ q, const float* __restrict__ k,
                             const int* __restrict__ src, const int* __restrict__ dst,
                             float* __restrict__ scores, float* __restrict__ m) {
    int e = (blockIdx.x * blockDim.x + threadIdx.x) >> 5;
    int lane = threadIdx.x & 31;
    if (e >= N_EDGES) return;
    int s = src[e], d = dst[e];
    float4 qv = *(const float4*)&q[(size_t)d * HID + lane * 4];
    float4 kv = *(const float4*)&k[(size_t)s * HID + lane * 4];
    float p = qv.x * kv.x + qv.y * kv.y + qv.z * kv.z + qv.w * kv.w;
    p += __shfl_xor_sync(0xffffffffu, p, 1);
    p += __shfl_xor_sync(0xffffffffu, p, 2);
    if ((lane & 3) == 0) {
        int hh = lane >> 2;
        float sc = p * 0.25f;
        scores[e * NH + hh] = sc;
        atomicMaxF(&m[d * NH + hh], sc);
    }
}

__global__ void expsum_kernel(float* __restrict__ scores, const float* __restrict__ m,
                              float* __restrict__ den, const int* __restrict__ dst) {
    int idx = blockIdx.x * blockDim.x + threadIdx.x;
    if (idx >= N_EDGES * NH) return;
    int e = idx >> 3, hh = idx & 7;
    int d = dst[e];
    float ex = __expf(scores[idx] - m[d * NH + hh]);
    scores[idx] = ex;
    atomicAdd(&den[d * NH + hh], ex);
}

__global__ void agg_kernel(const float* __restrict__ scores, const float* __restrict__ den,
                           const float* __restrict__ v, const int* __restrict__ src,
                           const int* __restrict__ dst, float* __restrict__ attn) {
    int e = (blockIdx.x * blockDim.x + threadIdx.x) >> 5;
    int lane = threadIdx.x & 31;
    if (e >= N_EDGES) return;
    int s = src[e], d = dst[e];
    int hh = lane >> 2;
    float w = scores[e * NH + hh] / den[d * NH + hh];
    float4 vv = *(const float4*)&v[(size_t)s * HID + lane * 4];
    float* dst_ptr = &attn[(size_t)d * HID + lane * 4];
    atomicAdd(dst_ptr + 0, w * vv.x);
    atomicAdd(dst_ptr + 1, w * vv.y);
    atomicAdd(dst_ptr + 2, w * vv.z);
    atomicAdd(dst_ptr + 3, w * vv.w);
}

// ---------------- classifier prep ----------------
__global__ void padW_kernel(const float* __restrict__ Wh, float* __restrict__ Wpad) {
    int idx = blockIdx.x * blockDim.x + threadIdx.x;
    if (idx >= 3 * MLP_K * MLP_LD) return;
    int i = idx / (MLP_K * MLP_LD);
    int rem = idx - i * (MLP_K * MLP_LD);
    int r = rem / MLP_LD, c = rem - r * MLP_LD;
    Wpad[idx] = (r < 285 && c < 285) ? Wh[i * 285 * 285 + r * 285 + c] : 0.0f;
}

__global__ void padb_kernel(const float* __restrict__ bh, float* __restrict__ bpad,
                            const float* __restrict__ Wo, float* __restrict__ Wopad) {
    int idx = blockIdx.x * blockDim.x + threadIdx.x;
    if (idx < 3 * MLP_LD) {
        int i = idx / MLP_LD, c = idx - i * MLP_LD;
        bpad[idx] = (c < 285) ? bh[i * 285 + c] : 0.0f;
    }
    if (idx < MLP_K * 2) {
        int r = idx >> 1;
        Wopad[idx] = (r < 285) ? Wo[idx] : 0.0f;
    }
}

__global__ void gather_kernel(const float* __restrict__ h, const float* __restrict__ ce,
                              const float* __restrict__ pe, const float* __restrict__ num,
                              const int* __restrict__ src, const int* __restrict__ dst,
                              const int* __restrict__ pc, const int* __restrict__ rc,
                              const int* __restrict__ pf, float* __restrict__ y) {
    size_t idx = (size_t)blockIdx.x * blockDim.x + threadIdx.x;
    if (idx >= (size_t)N_EDGES * MLP_LD) return;
    int e = (int)(idx / MLP_LD);
    int c = (int)(idx - (size_t)e * MLP_LD);
    float val;
    if (c < 128)       val = h[(size_t)src[e] * HID + c];
    else if (c < 256)  val = h[(size_t)dst[e] * HID + (c - 128)];
    else if (c < 264)  val = ce[pc[e] * 8 + (c - 256)];
    else if (c < 272)  val = ce[rc[e] * 8 + (c - 264)];
    else if (c < 280)  val = pe[pf[e] * 8 + (c - 272)];
    else if (c < 285)  val = num[(size_t)e * 5 + (c - 280)];
    else               val = 0.0f;
    y[idx] = val;
}

// ---------------- final projection ----------------
__global__ void out_kernel(const float* __restrict__ y, const float* __restrict__ Wo,
                           const float* __restrict__ bo, float* __restrict__ out) {
    __shared__ float Ws[MLP_K * 2];
    int tid = threadIdx.x;
    for (int i = tid; i < MLP_K * 2; i += blockDim.x) Ws[i] = Wo[i];
    __syncthreads();
    int e = (blockIdx.x * blockDim.x + tid) >> 5;
    int lane = tid & 31;
    if (e >= N_EDGES) return;
    const float* yr = &y[(size_t)e * MLP_LD];
    float a0 = 0.f, a1 = 0.f;
    #pragma unroll
    for (int kk = lane; kk < MLP_K; kk += 32) {
        float yv = yr[kk];
        a0 = fmaf(yv, Ws[kk * 2 + 0], a0);
        a1 = fmaf(yv, Ws[kk * 2 + 1], a1);
    }
    #pragma unroll
    for (int o = 16; o; o >>= 1) {
        a0 += __shfl_xor_sync(0xffffffffu, a0, o);
        a1 += __shfl_xor_sync(0xffffffffu, a1, o);
    }
    if (lane == 0) {
        out[e * 2 + 0] = a0 + bo[0];
        out[e * 2 + 1] = a1 + bo[1];
    }
}

// ---------------- host ----------------
static inline int G(long long n) { return (int)((n + 255) / 256); }

extern "C" void kernel_launch(void* const* d_in, const int* in_sizes, int n_in,
                              void* d_out, int out_size) {
    const float* node_feats = (const float*)d_in[0];
    const float* numericals = (const float*)d_in[1];
    const float* W_emb = (const float*)d_in[2];
    const float* b_emb = (const float*)d_in[3];
    const float* WQ = (const float*)d_in[4];
    const float* bQ = (const float*)d_in[5];
    const float* WK = (const float*)d_in[6];
    const float* bK = (const float*)d_in[7];
    const float* WV = (const float*)d_in[8];
    const float* bV = (const float*)d_in[9];
    const float* WO = (const float*)d_in[10];
    const float* bO = (const float*)d_in[11];
    const float* ln1_g = (const float*)d_in[12];
    const float* ln1_b = (const float*)d_in[13];
    const float* ln2_g = (const float*)d_in[14];
    const float* ln2_b = (const float*)d_in[15];
    const float* W1 = (const float*)d_in[16];
    const float* b1 = (const float*)d_in[17];
    const float* W2 = (const float*)d_in[18];
    const float* b2 = (const float*)d_in[19];
    const float* curr_emb = (const float*)d_in[20];
    const float* pay_emb = (const float*)d_in[21];
    const float* mlp_Wh = (const float*)d_in[22];
    const float* mlp_bh = (const float*)d_in[23];
    const float* mlp_Wo = (const float*)d_in[24];
    const float* mlp_bo = (const float*)d_in[25];
    const int* src = (const int*)d_in[26];
    const int* dst = (const int*)d_in[27];
    const int* pc = (const int*)d_in[28];
    const int* rc = (const int*)d_in[29];
    const int* pf = (const int*)d_in[30];
    float* out = (float*)d_out;

    float *h, *x, *q, *k, *v, *attn, *tmp, *sc, *m, *den, *y0, *y1, *Wpad, *bpad, *Wopad;
    cudaGetSymbolAddress((void**)&h, g_h);
    cudaGetSymbolAddress((void**)&x, g_x);
    cudaGetSymbolAddress((void**)&q, g_q);
    cudaGetSymbolAddress((void**)&k, g_k);
    cudaGetSymbolAddress((void**)&v, g_v);
    cudaGetSymbolAddress((void**)&attn, g_attn);
    cudaGetSymbolAddress((void**)&tmp, g_tmp);
    cudaGetSymbolAddress((void**)&sc, g_sc);
    cudaGetSymbolAddress((void**)&m, g_m);
    cudaGetSymbolAddress((void**)&den, g_den);
    cudaGetSymbolAddress((void**)&y0, g_y0);
    cudaGetSymbolAddress((void**)&y1, g_y1);
    cudaGetSymbolAddress((void**)&Wpad, g_Wpad);
    cudaGetSymbolAddress((void**)&bpad, g_bpad);
    cudaGetSymbolAddress((void**)&Wopad, g_Wopad);

    padW_kernel<<<G(3 * MLP_K * MLP_LD), 256>>>(mlp_Wh, Wpad);
    padb_kernel<<<G(3 * MLP_LD), 256>>>(mlp_bh, bpad, mlp_Wo, Wopad);

    embed_kernel<<<G((long long)N_NODES * HID), 256>>>(node_feats, W_emb, b_emb, h);

    auto gemm = [&](const float* A, const float* W, const float* bias, const float* res,
                    float* C, int M, int K, int ldA, int Ncols, int relu) {
        dim3 grid(Ncols / BN, (M + BM - 1) / BM);
        gemm_kernel<<<grid, 256>>>(A, W, bias, res, C, M, K, ldA, Ncols, relu);
    };

    for (int l = 0; l < LAYERS; l++) {
        const int WOFF = l * HID * HID, BOFF = l * HID;
        ln_kernel<<<G((long long)N_NODES * 32), 256>>>(h, ln1_g + BOFF, ln1_b + BOFF, x);
        gemm(x, WQ + WOFF, bQ + BOFF, nullptr, q, N_NODES, HID, HID, HID, 0);
        gemm(x, WK + WOFF, bK + BOFF, nullptr, k, N_NODES, HID, HID, HID, 0);
        gemm(x, WV + WOFF, bV + BOFF, nullptr, v, N_NODES, HID, HID, HID, 0);
        init_attn_kernel<<<G((long long)N_NODES * HID), 256>>>(m, den, attn);
        score_kernel<<<G((long long)N_EDGES * 32), 256>>>(q, k, src, dst, sc, m);
        expsum_kernel<<<G((long long)N_EDGES * NH), 256>>>(sc, m, den, dst);
        agg_kernel<<<G((long long)N_EDGES * 32), 256>>>(sc, den, v, src, dst, attn);
        gemm(attn, WO + WOFF, bO + BOFF, h, h, N_NODES, HID, HID, HID, 0);
        ln_kernel<<<G((long long)N_NODES * 32), 256>>>(h, ln2_g + BOFF, ln2_b + BOFF, x);
        gemm(x, W1 + WOFF, b1 + BOFF, nullptr, tmp, N_NODES, HID, HID, HID, 1);
        gemm(tmp, W2 + WOFF, b2 + BOFF, h, h, N_NODES, HID, HID, HID, 0);
    }

    // edge classifier: gather + 3 tf32 tensor-core GEMMs + projection
    gather_kernel<<<G((long long)N_EDGES * MLP_LD), 256>>>(
        h, curr_emb, pay_emb, numericals, src, dst, pc, rc, pf, y0);

    dim3 mgrid(GN / 64, (N_EDGES + 127) / 128);
    mma_gemm_kernel<<<mgrid, 128>>>(y0, Wpad + 0 * MLP_K * MLP_LD, bpad + 0 * MLP_LD,
                                    y1, N_EDGES);
    mma_gemm_kernel<<<mgrid, 128>>>(y1, Wpad + 1 * MLP_K * MLP_LD, bpad + 1 * MLP_LD,
                                    y0, N_EDGES);
    mma_gemm_kernel<<<mgrid, 128>>>(y0, Wpad + 2 * MLP_K * MLP_LD, bpad + 2 * MLP_LD,
                                    y1, N_EDGES);

    out_kernel<<<G((long long)N_EDGES * 32), 256>>>(y1, Wopad, mlp_bo, out);
}

// round 5
// speedup vs baseline: 2.0465x; 1.6626x over previous
#include <cuda_runtime.h>
#include <cstdint>
#include <cstddef>

#define N_NODES 20000
#define N_EDGES 200000
#define HID 128
#define NH 8
#define LAYERS 7
#define MLP_K 288      // padded K (285 -> 288)
#define MLP_LD 320     // padded row stride / N

// ---------------- scratch (static device globals) ----------------
__device__ float g_h[N_NODES * HID];
__device__ float g_x[N_NODES * HID];
__device__ float g_qkv[N_NODES * 384];
__device__ float g_attn[N_NODES * HID];
__device__ float g_tmp[N_NODES * HID];
__device__ float g_y0[(size_t)N_EDGES * MLP_LD];
__device__ float g_y1[(size_t)N_EDGES * MLP_LD];
__device__ float g_Wpad[3 * MLP_K * MLP_LD];
__device__ float g_bpad[3 * MLP_LD];
__device__ float g_Wopad[MLP_K * 2];
__device__ float g_Wqkv[LAYERS * HID * 384];
__device__ float g_bqkv[LAYERS * 384];
__device__ float g_ns[(size_t)N_NODES * MLP_LD];
__device__ float g_nd[(size_t)N_NODES * MLP_LD];
__device__ float g_tpc[15 * MLP_LD];
__device__ float g_trc[15 * MLP_LD];
__device__ float g_tpf[7 * MLP_LD];
__device__ float g_zero[MLP_LD];
__device__ int   g_deg[N_NODES];
__device__ int   g_rowptr[N_NODES + 1];
__device__ int   g_cursor[N_NODES];
__device__ int   g_srcs[N_EDGES];

__device__ __forceinline__ float tf32r(float x) {
    unsigned u;
    asm("cvt.rna.tf32.f32 %0, %1;" : "=r"(u) : "f"(x));
    return __uint_as_float(u);
}

// ---------------- embedding ----------------
__global__ void embed_kernel(const float* __restrict__ nf, const float* __restrict__ We,
                             const float* __restrict__ be, float* __restrict__ h) {
    int idx = blockIdx.x * blockDim.x + threadIdx.x;
    if (idx >= N_NODES * HID) return;
    int n = idx >> 7, c = idx & 127;
    h[idx] = fmaf(nf[n * 2 + 0], We[c], fmaf(nf[n * 2 + 1], We[HID + c], be[c]));
}

// ---------------- LayerNorm: warp per node ----------------
__global__ void ln_kernel(const float* __restrict__ h, const float* __restrict__ g,
                          const float* __restrict__ b, float* __restrict__ x) {
    int node = (blockIdx.x * blockDim.x + threadIdx.x) >> 5;
    int lane = threadIdx.x & 31;
    if (node >= N_NODES) return;
    float4 v = *(const float4*)&h[node * HID + lane * 4];
    float s = v.x + v.y + v.z + v.w;
    #pragma unroll
    for (int o = 16; o; o >>= 1) s += __shfl_xor_sync(0xffffffffu, s, o);
    float mu = s * (1.0f / 128.0f);
    float dx = v.x - mu, dy = v.y - mu, dz = v.z - mu, dw = v.w - mu;
    float q = dx * dx + dy * dy + dz * dz + dw * dw;
    #pragma unroll
    for (int o = 16; o; o >>= 1) q += __shfl_xor_sync(0xffffffffu, q, o);
    float rs = rsqrtf(q * (1.0f / 128.0f) + 1e-5f);
    float4 gv = *(const float4*)&g[lane * 4];
    float4 bv = *(const float4*)&b[lane * 4];
    float4 o4;
    o4.x = fmaf(dx * rs, gv.x, bv.x);
    o4.y = fmaf(dy * rs, gv.y, bv.y);
    o4.z = fmaf(dz * rs, gv.z, bv.z);
    o4.w = fmaf(dw * rs, gv.w, bv.w);
    *(float4*)&x[node * HID + lane * 4] = o4;
}

// ---------------- tiled fp32 GEMM (node pipeline) ----------------
#define BM 128
#define BN 64
#define BK 16
#define TM 8
#define TN 4

__global__ __launch_bounds__(256)
void gemm_kernel(const float* __restrict__ A, const float* __restrict__ W,
                 const float* __restrict__ bias, const float* __restrict__ res,
                 float* __restrict__ C, int M, int K, int ldA, int N, int relu) {
    __shared__ float As[BK][BM + 4];
    __shared__ float Bs[BK][BN];
    int tid = threadIdx.x;
    int tx = tid & 15;
    int ty = tid >> 4;
    int rowBase = blockIdx.y * BM;
    int colBase = blockIdx.x * BN;

    float acc[TM][TN];
    #pragma unroll
    for (int i = 0; i < TM; i++)
        #pragma unroll
        for (int j = 0; j < TN; j++) acc[i][j] = 0.0f;

    for (int k0 = 0; k0 < K; k0 += BK) {
        #pragma unroll
        for (int it = 0; it < 2; it++) {
            int i4 = tid + it * 256;
            int r = i4 >> 2;
            int c4 = (i4 & 3) * 4;
            int gr = rowBase + r;
            float4 v = make_float4(0.f, 0.f, 0.f, 0.f);
            if (gr < M) v = *(const float4*)&A[(size_t)gr * ldA + k0 + c4];
            As[c4 + 0][r] = v.x; As[c4 + 1][r] = v.y;
            As[c4 + 2][r] = v.z; As[c4 + 3][r] = v.w;
        }
        {
            int r = tid >> 4;
            int c4 = (tid & 15) * 4;
            float4 v = *(const float4*)&W[(size_t)(k0 + r) * N + colBase + c4];
            *(float4*)&Bs[r][c4] = v;
        }
        __syncthreads();
        #pragma unroll
        for (int kk = 0; kk < BK; kk++) {
            float4 a0 = *(const float4*)&As[kk][ty * TM];
            float4 a1 = *(const float4*)&As[kk][ty * TM + 4];
            float4 b0 = *(const float4*)&Bs[kk][tx * TN];
            float a[TM] = {a0.x, a0.y, a0.z, a0.w, a1.x, a1.y, a1.z, a1.w};
            float b[TN] = {b0.x, b0.y, b0.z, b0.w};
            #pragma unroll
            for (int i = 0; i < TM; i++)
                #pragma unroll
                for (int j = 0; j < TN; j++)
                    acc[i][j] = fmaf(a[i], b[j], acc[i][j]);
        }
        __syncthreads();
    }

    int gc = colBase + tx * TN;
    float4 bv = *(const float4*)&bias[gc];
    #pragma unroll
    for (int i = 0; i < TM; i++) {
        int gr = rowBase + ty * TM + i;
        if (gr >= M) continue;
        float4 o;
        o.x = acc[i][0] + bv.x; o.y = acc[i][1] + bv.y;
        o.z = acc[i][2] + bv.z; o.w = acc[i][3] + bv.w;
        if (res) {
            float4 rv = *(const float4*)&res[(size_t)gr * N + gc];
            o.x += rv.x; o.y += rv.y; o.z += rv.z; o.w += rv.w;
        }
        if (relu) {
            o.x = fmaxf(o.x, 0.f); o.y = fmaxf(o.y, 0.f);
            o.z = fmaxf(o.z, 0.f); o.w = fmaxf(o.w, 0.f);
        }
        *(float4*)&C[(size_t)gr * N + gc] = o;
    }
}

// ---------------- tf32 tensor-core GEMM (MLP layers 2,3) ----------------
// C[M,320] = relu(A[M,320(K=288)] @ W[288,320] + bias)
// 256 threads, 8 warps (2M x 4N), block tile 128x160, warp tile 64x40.
#define GK 288
#define GN 320
#define MBN 160
#define ASTRIDE 20
#define BSTRIDE 168   // 160 + 8: conflict-free B-fragment reads

__global__ __launch_bounds__(256)
void mma_gemm_kernel(const float* __restrict__ A, const float* __restrict__ W,
                     const float* __restrict__ bias, float* __restrict__ C, int M) {
    __shared__ float As[2][128][ASTRIDE];
    __shared__ float Bs[2][16][BSTRIDE];

    int tid = threadIdx.x;
    int lane = tid & 31, warp = tid >> 5;
    int warpM = warp & 1, warpN = warp >> 1;     // 2 x 4
    int rowBase = blockIdx.y * 128;
    int colBase = blockIdx.x * MBN;
    int gq = lane >> 2, tg = lane & 3;

    float acc[4][5][4];
    #pragma unroll
    for (int mi = 0; mi < 4; mi++)
        #pragma unroll
        for (int ni = 0; ni < 5; ni++)
            #pragma unroll
            for (int r = 0; r < 4; r++) acc[mi][ni][r] = 0.0f;

    // A staging: 512 float4, 2 iters; thread -> (row = idx>>2, c4 = (idx&3)*4)
    int ar[2], ac[2];
    bool av[2];
    #pragma unroll
    for (int it = 0; it < 2; it++) {
        int idx = tid + it * 256;
        ar[it] = idx >> 2; ac[it] = (idx & 3) * 4;
        av[it] = (rowBase + ar[it]) < M;
    }
    // B staging: 640 float4, 3 iters (last partial)
    int br[3], bc4[3];
    bool bvld[3];
    #pragma unroll
    for (int it = 0; it < 3; it++) {
        int idx = tid + it * 256;
        bvld[it] = idx < 640;
        br[it] = idx / 40; bc4[it] = (idx % 40) * 4;
    }

    float4 ra[2], rb[3];
    #pragma unroll
    for (int it = 0; it < 2; it++)
        ra[it] = av[it] ? *(const float4*)&A[(size_t)(rowBase + ar[it]) * GN + ac[it]]
                        : make_float4(0.f, 0.f, 0.f, 0.f);
    #pragma unroll
    for (int it = 0; it < 3; it++)
        rb[it] = bvld[it] ? *(const float4*)&W[(size_t)br[it] * GN + colBase + bc4[it]]
                          : make_float4(0.f, 0.f, 0.f, 0.f);

    #pragma unroll
    for (int it = 0; it < 2; it++) {
        As[0][ar[it]][ac[it] + 0] = tf32r(ra[it].x);
        As[0][ar[it]][ac[it] + 1] = tf32r(ra[it].y);
        As[0][ar[it]][ac[it] + 2] = tf32r(ra[it].z);
        As[0][ar[it]][ac[it] + 3] = tf32r(ra[it].w);
    }
    #pragma unroll
    for (int it = 0; it < 3; it++) {
        if (!bvld[it]) continue;
        Bs[0][br[it]][bc4[it] + 0] = tf32r(rb[it].x);
        Bs[0][br[it]][bc4[it] + 1] = tf32r(rb[it].y);
        Bs[0][br[it]][bc4[it] + 2] = tf32r(rb[it].z);
        Bs[0][br[it]][bc4[it] + 3] = tf32r(rb[it].w);
    }
    __syncthreads();

    const int NCHUNK = GK / 16;   // 18
    #pragma unroll 1
    for (int c = 0; c < NCHUNK; c++) {
        int cur = c & 1;
        if (c < NCHUNK - 1) {
            int k0 = (c + 1) * 16;
            #pragma unroll
            for (int it = 0; it < 2; it++)
                ra[it] = av[it]
                    ? *(const float4*)&A[(size_t)(rowBase + ar[it]) * GN + k0 + ac[it]]
                    : make_float4(0.f, 0.f, 0.f, 0.f);
            #pragma unroll
            for (int it = 0; it < 3; it++)
                rb[it] = bvld[it]
                    ? *(const float4*)&W[(size_t)(k0 + br[it]) * GN + colBase + bc4[it]]
                    : make_float4(0.f, 0.f, 0.f, 0.f);
        }

        #pragma unroll
        for (int kk = 0; kk < 16; kk += 8) {
            unsigned af[4][4];
            #pragma unroll
            for (int mi = 0; mi < 4; mi++) {
                int r = warpM * 64 + mi * 16 + gq;
                int cc = kk + tg;
                af[mi][0] = __float_as_uint(As[cur][r][cc]);
                af[mi][1] = __float_as_uint(As[cur][r + 8][cc]);
                af[mi][2] = __float_as_uint(As[cur][r][cc + 4]);
                af[mi][3] = __float_as_uint(As[cur][r + 8][cc + 4]);
            }
            #pragma unroll
            for (int ni = 0; ni < 5; ni++) {
                int bc = warpN * 40 + ni * 8 + gq;
                unsigned b0 = __float_as_uint(Bs[cur][kk + tg][bc]);
                unsigned b1 = __float_as_uint(Bs[cur][kk + tg + 4][bc]);
                #pragma unroll
                for (int mi = 0; mi < 4; mi++) {
                    asm volatile(
                        "mma.sync.aligned.m16n8k8.row.col.f32.tf32.tf32.f32 "
                        "{%0,%1,%2,%3},{%4,%5,%6,%7},{%8,%9},{%0,%1,%2,%3};"
                        : "+f"(acc[mi][ni][0]), "+f"(acc[mi][ni][1]),
                          "+f"(acc[mi][ni][2]), "+f"(acc[mi][ni][3])
                        : "r"(af[mi][0]), "r"(af[mi][1]), "r"(af[mi][2]), "r"(af[mi][3]),
                          "r"(b0), "r"(b1));
                }
            }
        }

        if (c < NCHUNK - 1) {
            int nxt = cur ^ 1;
            #pragma unroll
            for (int it = 0; it < 2; it++) {
                As[nxt][ar[it]][ac[it] + 0] = tf32r(ra[it].x);
                As[nxt][ar[it]][ac[it] + 1] = tf32r(ra[it].y);
                As[nxt][ar[it]][ac[it] + 2] = tf32r(ra[it].z);
                As[nxt][ar[it]][ac[it] + 3] = tf32r(ra[it].w);
            }
            #pragma unroll
            for (int it = 0; it < 3; it++) {
                if (!bvld[it]) continue;
                Bs[nxt][br[it]][bc4[it] + 0] = tf32r(rb[it].x);
                Bs[nxt][br[it]][bc4[it] + 1] = tf32r(rb[it].y);
                Bs[nxt][br[it]][bc4[it] + 2] = tf32r(rb[it].z);
                Bs[nxt][br[it]][bc4[it] + 3] = tf32r(rb[it].w);
            }
            __syncthreads();
        }
    }

    #pragma unroll
    for (int ni = 0; ni < 5; ni++) {
        int gc = colBase + warpN * 40 + ni * 8 + 2 * tg;
        float2 bv = *(const float2*)&bias[gc];
        #pragma unroll
        for (int mi = 0; mi < 4; mi++) {
            int r0 = rowBase + warpM * 64 + mi * 16 + gq;
            if (r0 < M) {
                float2 o;
                o.x = fmaxf(acc[mi][ni][0] + bv.x, 0.f);
                o.y = fmaxf(acc[mi][ni][1] + bv.y, 0.f);
                *(float2*)&C[(size_t)r0 * GN + gc] = o;
            }
            int r1 = r0 + 8;
            if (r1 < M) {
                float2 o;
                o.x = fmaxf(acc[mi][ni][2] + bv.x, 0.f);
                o.y = fmaxf(acc[mi][ni][3] + bv.y, 0.f);
                *(float2*)&C[(size_t)r1 * GN + gc] = o;
            }
        }
    }
}

// ---------------- CSR build ----------------
__global__ void deg_zero_kernel(int* __restrict__ deg) {
    int i = blockIdx.x * blockDim.x + threadIdx.x;
    if (i < N_NODES) deg[i] = 0;
}
__global__ void deg_count_kernel(const int* __restrict__ dst, int* __restrict__ deg) {
    int e = blockIdx.x * blockDim.x + threadIdx.x;
    if (e < N_EDGES) atomicAdd(&deg[dst[e]], 1);
}
// exclusive scan over 20000 ints, single block of 1024 threads
__global__ void scan_kernel(const int* __restrict__ deg, int* __restrict__ rowptr) {
    __shared__ int sums[1024];
    const int CH = (N_NODES + 1023) / 1024;   // 20
    int t = threadIdx.x;
    int base = t * CH;
    int local[CH];
    int s = 0;
    #pragma unroll
    for (int i = 0; i < CH; i++) {
        int idx = base + i;
        local[i] = (idx < N_NODES) ? deg[idx] : 0;
        s += local[i];
    }
    sums[t] = s;
    __syncthreads();
    for (int off = 1; off < 1024; off <<= 1) {
        int v = (t >= off) ? sums[t - off] : 0;
        __syncthreads();
        sums[t] += v;
        __syncthreads();
    }
    int run = sums[t] - s;   // exclusive prefix at base
    #pragma unroll
    for (int i = 0; i < CH; i++) {
        int idx = base + i;
        if (idx < N_NODES) rowptr[idx] = run;
        run += local[i];
    }
    if (t == 1023) rowptr[N_NODES] = sums[1023];
}
__global__ void cursor_kernel(const int* __restrict__ rowptr, int* __restrict__ cur) {
    int i = blockIdx.x * blockDim.x + threadIdx.x;
    if (i < N_NODES) cur[i] = rowptr[i];
}
__global__ void scatter_kernel(const int* __restrict__ src, const int* __restrict__ dst,
                               int* __restrict__ cur, int* __restrict__ srcs) {
    int e = blockIdx.x * blockDim.x + threadIdx.x;
    if (e >= N_EDGES) return;
    int pos = atomicAdd(&cur[dst[e]], 1);
    srcs[pos] = src[e];
}

// ---------------- fused attention: warp per dst node, online softmax ----------------
// qkv[n, 0:128]=Q, [128:256]=K, [256:384]=V
__global__ void attn_kernel(const float* __restrict__ qkv, const int* __restrict__ rowptr,
                            const int* __restrict__ srcs, float* __restrict__ attn) {
    int d = (blockIdx.x * blockDim.x + threadIdx.x) >> 5;
    int lane = threadIdx.x & 31;
    if (d >= N_NODES) return;
    int beg = rowptr[d], end = rowptr[d + 1];
    if (beg == end) {
        *(float4*)&attn[(size_t)d * HID + lane * 4] = make_float4(0.f, 0.f, 0.f, 0.f);
        return;
    }
    float4 qv = *(const float4*)&qkv[(size_t)d * 384 + lane * 4];
    float m = -3.4e38f, den = 0.f;
    float4 acc = make_float4(0.f, 0.f, 0.f, 0.f);
    for (int j = beg; j < end; j++) {
        int s = srcs[j];
        float4 kv = *(const float4*)&qkv[(size_t)s * 384 + 128 + lane * 4];
        float4 vv = *(const float4*)&qkv[(size_t)s * 384 + 256 + lane * 4];
        float p = qv.x * kv.x + qv.y * kv.y + qv.z * kv.z + qv.w * kv.w;
        p += __shfl_xor_sync(0xffffffffu, p, 1);
        p += __shfl_xor_sync(0xffffffffu, p, 2);
        float sc = p * 0.25f;                 // / sqrt(DH=16)
        float nm = fmaxf(m, sc);
        float scale = __expf(m - nm);         // first iter: exp(-inf)=0
        float ex = __expf(sc - nm);
        acc.x = acc.x * scale + ex * vv.x;
        acc.y = acc.y * scale + ex * vv.y;
        acc.z = acc.z * scale + ex * vv.z;
        acc.w = acc.w * scale + ex * vv.w;
        den = den * scale + ex;
        m = nm;
    }
    float inv = 1.0f / den;
    float4 o = make_float4(acc.x * inv, acc.y * inv, acc.z * inv, acc.w * inv);
    *(float4*)&attn[(size_t)d * HID + lane * 4] = o;
}

// ---------------- weight prep ----------------
__global__ void padW_kernel(const float* __restrict__ Wh, float* __restrict__ Wpad) {
    int idx = blockIdx.x * blockDim.x + threadIdx.x;
    if (idx >= 3 * MLP_K * MLP_LD) return;
    int i = idx / (MLP_K * MLP_LD);
    int rem = idx - i * (MLP_K * MLP_LD);
    int r = rem / MLP_LD, c = rem - r * MLP_LD;
    Wpad[idx] = (r < 285 && c < 285) ? Wh[i * 285 * 285 + r * 285 + c] : 0.0f;
}

__global__ void padb_kernel(const float* __restrict__ bh, float* __restrict__ bpad,
                            const float* __restrict__ Wo, float* __restrict__ Wopad,
                            float* __restrict__ zero) {
    int idx = blockIdx.x * blockDim.x + threadIdx.x;
    if (idx < 3 * MLP_LD) {
        int i = idx / MLP_LD, c = idx - i * MLP_LD;
        bpad[idx] = (c < 285) ? bh[i * 285 + c] : 0.0f;
    }
    if (idx < MLP_K * 2) {
        int r = idx >> 1;
        Wopad[idx] = (r < 285) ? Wo[idx] : 0.0f;
    }
    if (idx < MLP_LD) zero[idx] = 0.0f;
}

__global__ void packqkv_kernel(const float* __restrict__ WQ, const float* __restrict__ WK,
                               const float* __restrict__ WV, const float* __restrict__ bQ,
                               const float* __restrict__ bK, const float* __restrict__ bV,
                               float* __restrict__ Wqkv, float* __restrict__ bqkv) {
    int idx = blockIdx.x * blockDim.x + threadIdx.x;
    if (idx < LAYERS * HID * 384) {
        int l = idx / (HID * 384);
        int rem = idx - l * (HID * 384);
        int r = rem / 384, c = rem - r * 384;
        float v;
        if (c < 128)      v = WQ[l * HID * HID + r * HID + c];
        else if (c < 256) v = WK[l * HID * HID + r * HID + (c - 128)];
        else              v = WV[l * HID * HID + r * HID + (c - 256)];
        Wqkv[idx] = v;
    }
    if (idx < LAYERS * 384) {
        int l = idx / 384, c = idx - l * 384;
        float v;
        if (c < 128)      v = bQ[l * HID + c];
        else if (c < 256) v = bK[l * HID + (c - 128)];
        else              v = bV[l * HID + (c - 256)];
        bqkv[idx] = v;
    }
}

// tables: tpc[i][c] = sum_k ce[i][k]*W0[(256+k)][c]; trc rows 264..271; tpf rows 272..279 (pe)
__global__ void tables_kernel(const float* __restrict__ ce, const float* __restrict__ pe,
                              const float* __restrict__ W0, float* __restrict__ tpc,
                              float* __restrict__ trc, float* __restrict__ tpf) {
    int idx = blockIdx.x * blockDim.x + threadIdx.x;
    if (idx >= 37 * MLP_LD) return;
    int i = idx / MLP_LD, c = idx - i * MLP_LD;
    if (i < 15) {
        float s = 0.f;
        #pragma unroll
        for (int k = 0; k < 8; k++) s = fmaf(ce[i * 8 + k], W0[(256 + k) * MLP_LD + c], s);
        tpc[i * MLP_LD + c] = s;
    } else if (i < 30) {
        int ii = i - 15;
        float s = 0.f;
        #pragma unroll
        for (int k = 0; k < 8; k++) s = fmaf(ce[ii * 8 + k], W0[(264 + k) * MLP_LD + c], s);
        trc[ii * MLP_LD + c] = s;
    } else {
        int ii = i - 30;
        float s = 0.f;
        #pragma unroll
        for (int k = 0; k < 8; k++) s = fmaf(pe[ii * 8 + k], W0[(272 + k) * MLP_LD + c], s);
        tpf[ii * MLP_LD + c] = s;
    }
}

// ---------------- MLP layer-1 assemble: warp per edge ----------------
__global__ void assemble_kernel(const float* __restrict__ ns, const float* __restrict__ nd,
                                const float* __restrict__ tpc, const float* __restrict__ trc,
                                const float* __restrict__ tpf, const float* __restrict__ W0,
                                const float* __restrict__ num, const int* __restrict__ src,
                                const int* __restrict__ dst, const int* __restrict__ pc,
                                const int* __restrict__ rc, const int* __restrict__ pf,
                                float* __restrict__ y) {
    int e = (blockIdx.x * blockDim.x + threadIdx.x) >> 5;
    int lane = threadIdx.x & 31;
    if (e >= N_EDGES) return;
    size_t so = (size_t)src[e] * MLP_LD;
    size_t doff = (size_t)dst[e] * MLP_LD;
    int ipc = pc[e] * MLP_LD, irc = rc[e] * MLP_LD, ipf = pf[e] * MLP_LD;
    float n0 = num[(size_t)e * 5 + 0], n1 = num[(size_t)e * 5 + 1];
    float n2 = num[(size_t)e * 5 + 2], n3 = num[(size_t)e * 5 + 3];
    float n4 = num[(size_t)e * 5 + 4];
    const float* Wn = W0 + 280 * MLP_LD;
    #pragma unroll
    for (int t = 0; t < 10; t++) {
        int c = t * 32 + lane;
        float val = ns[so + c] + nd[doff + c] + tpc[ipc + c] + trc[irc + c] + tpf[ipf + c];
        val = fmaf(n0, Wn[c], val);
        val = fmaf(n1, Wn[MLP_LD + c], val);
        val = fmaf(n2, Wn[2 * MLP_LD + c], val);
        val = fmaf(n3, Wn[3 * MLP_LD + c], val);
        val = fmaf(n4, Wn[4 * MLP_LD + c], val);
        y[(size_t)e * MLP_LD + c] = fmaxf(val, 0.f);
    }
}

// ---------------- final projection ----------------
__global__ void out_kernel(const float* __restrict__ y, const float* __restrict__ Wo,
                           const float* __restrict__ bo, float* __restrict__ out) {
    __shared__ float Ws[MLP_K * 2];
    int tid = threadIdx.x;
    for (int i = tid; i < MLP_K * 2; i += blockDim.x) Ws[i] = Wo[i];
    __syncthreads();
    int e = (blockIdx.x * blockDim.x + tid) >> 5;
    int lane = tid & 31;
    if (e >= N_EDGES) return;
    const float* yr = &y[(size_t)e * MLP_LD];
    float a0 = 0.f, a1 = 0.f;
    #pragma unroll
    for (int kk = lane; kk < MLP_K; kk += 32) {
        float yv = yr[kk];
        a0 = fmaf(yv, Ws[kk * 2 + 0], a0);
        a1 = fmaf(yv, Ws[kk * 2 + 1], a1);
    }
    #pragma unroll
    for (int o = 16; o; o >>= 1) {
        a0 += __shfl_xor_sync(0xffffffffu, a0, o);
        a1 += __shfl_xor_sync(0xffffffffu, a1, o);
    }
    if (lane == 0) {
        out[e * 2 + 0] = a0 + bo[0];
        out[e * 2 + 1] = a1 + bo[1];
    }
}

// ---------------- host ----------------
static inline int G(long long n) { return (int)((n + 255) / 256); }

extern "C" void kernel_launch(void* const* d_in, const int* in_sizes, int n_in,
                              void* d_out, int out_size) {
    const float* node_feats = (const float*)d_in[0];
    const float* numericals = (const float*)d_in[1];
    const float* W_emb = (const float*)d_in[2];
    const float* b_emb = (const float*)d_in[3];
    const float* WQ = (const float*)d_in[4];
    const float* bQ = (const float*)d_in[5];
    const float* WK = (const float*)d_in[6];
    const float* bK = (const float*)d_in[7];
    const float* WV = (const float*)d_in[8];
    const float* bV = (const float*)d_in[9];
    const float* WO = (const float*)d_in[10];
    const float* bO = (const float*)d_in[11];
    const float* ln1_g = (const float*)d_in[12];
    const float* ln1_b = (const float*)d_in[13];
    const float* ln2_g = (const float*)d_in[14];
    const float* ln2_b = (const float*)d_in[15];
    const float* W1 = (const float*)d_in[16];
    const float* b1 = (const float*)d_in[17];
    const float* W2 = (const float*)d_in[18];
    const float* b2 = (const float*)d_in[19];
    const float* curr_emb = (const float*)d_in[20];
    const float* pay_emb = (const float*)d_in[21];
    const float* mlp_Wh = (const float*)d_in[22];
    const float* mlp_bh = (const float*)d_in[23];
    const float* mlp_Wo = (const float*)d_in[24];
    const float* mlp_bo = (const float*)d_in[25];
    const int* src = (const int*)d_in[26];
    const int* dst = (const int*)d_in[27];
    const int* pc = (const int*)d_in[28];
    const int* rc = (const int*)d_in[29];
    const int* pf = (const int*)d_in[30];
    float* out = (float*)d_out;

    float *h, *x, *qkv, *attn, *tmp, *y0, *y1, *Wpad, *bpad, *Wopad;
    float *Wqkv, *bqkv, *ns, *nd, *tpc, *trc, *tpf, *zero;
    int *deg, *rowptr, *cursor, *srcs;
    cudaGetSymbolAddress((void**)&h, g_h);
    cudaGetSymbolAddress((void**)&x, g_x);
    cudaGetSymbolAddress((void**)&qkv, g_qkv);
    cudaGetSymbolAddress((void**)&attn, g_attn);
    cudaGetSymbolAddress((void**)&tmp, g_tmp);
    cudaGetSymbolAddress((void**)&y0, g_y0);
    cudaGetSymbolAddress((void**)&y1, g_y1);
    cudaGetSymbolAddress((void**)&Wpad, g_Wpad);
    cudaGetSymbolAddress((void**)&bpad, g_bpad);
    cudaGetSymbolAddress((void**)&Wopad, g_Wopad);
    cudaGetSymbolAddress((void**)&Wqkv, g_Wqkv);
    cudaGetSymbolAddress((void**)&bqkv, g_bqkv);
    cudaGetSymbolAddress((void**)&ns, g_ns);
    cudaGetSymbolAddress((void**)&nd, g_nd);
    cudaGetSymbolAddress((void**)&tpc, g_tpc);
    cudaGetSymbolAddress((void**)&trc, g_trc);
    cudaGetSymbolAddress((void**)&tpf, g_tpf);
    cudaGetSymbolAddress((void**)&zero, g_zero);
    cudaGetSymbolAddress((void**)&deg, g_deg);
    cudaGetSymbolAddress((void**)&rowptr, g_rowptr);
    cudaGetSymbolAddress((void**)&cursor, g_cursor);
    cudaGetSymbolAddress((void**)&srcs, g_srcs);

    // ---- one-time prep (per launch) ----
    padW_kernel<<<G(3 * MLP_K * MLP_LD), 256>>>(mlp_Wh, Wpad);
    padb_kernel<<<G(3 * MLP_LD), 256>>>(mlp_bh, bpad, mlp_Wo, Wopad, zero);
    packqkv_kernel<<<G((long long)LAYERS * HID * 384), 256>>>(WQ, WK, WV, bQ, bK, bV,
                                                              Wqkv, bqkv);
    tables_kernel<<<G(37 * MLP_LD), 256>>>(curr_emb, pay_emb, Wpad, tpc, trc, tpf);

    // CSR build
    deg_zero_kernel<<<G(N_NODES), 256>>>(deg);
    deg_count_kernel<<<G(N_EDGES), 256>>>(dst, deg);
    scan_kernel<<<1, 1024>>>(deg, rowptr);
    cursor_kernel<<<G(N_NODES), 256>>>(rowptr, cursor);
    scatter_kernel<<<G(N_EDGES), 256>>>(src, dst, cursor, srcs);

    embed_kernel<<<G((long long)N_NODES * HID), 256>>>(node_feats, W_emb, b_emb, h);

    auto gemm = [&](const float* A, const float* W, const float* bias, const float* res,
                    float* C, int M, int K, int ldA, int Ncols, int relu) {
        dim3 grid(Ncols / BN, (M + BM - 1) / BM);
        gemm_kernel<<<grid, 256>>>(A, W, bias, res, C, M, K, ldA, Ncols, relu);
    };

    for (int l = 0; l < LAYERS; l++) {
        const int WOFF = l * HID * HID, BOFF = l * HID;
        ln_kernel<<<G((long long)N_NODES * 32), 256>>>(h, ln1_g + BOFF, ln1_b + BOFF, x);
        gemm(x, Wqkv + l * HID * 384, bqkv + l * 384, nullptr, qkv,
             N_NODES, HID, HID, 384, 0);
        attn_kernel<<<G((long long)N_NODES * 32), 256>>>(qkv, rowptr, srcs, attn);
        gemm(attn, WO + WOFF, bO + BOFF, h, h, N_NODES, HID, HID, HID, 0);
        ln_kernel<<<G((long long)N_NODES * 32), 256>>>(h, ln2_g + BOFF, ln2_b + BOFF, x);
        gemm(x, W1 + WOFF, b1 + BOFF, nullptr, tmp, N_NODES, HID, HID, HID, 1);
        gemm(tmp, W2 + WOFF, b2 + BOFF, h, h, N_NODES, HID, HID, HID, 0);
    }

    // ---- edge classifier ----
    // layer 1 decomposed: per-node projections + table lookups + fused assemble (exact fp32)
    gemm(h, Wpad, bpad, nullptr, ns, N_NODES, HID, HID, MLP_LD, 0);                  // W0 rows 0:128
    gemm(h, Wpad + 128 * MLP_LD, zero, nullptr, nd, N_NODES, HID, HID, MLP_LD, 0);   // rows 128:256
    assemble_kernel<<<G((long long)N_EDGES * 32), 256>>>(
        ns, nd, tpc, trc, tpf, Wpad, numericals, src, dst, pc, rc, pf, y0);

    // layers 2,3: tf32 tensor-core GEMMs (BN=160 -> 2 column passes)
    dim3 mgrid(GN / MBN, (N_EDGES + 127) / 128);
    mma_gemm_kernel<<<mgrid, 256>>>(y0, Wpad + 1 * MLP_K * MLP_LD, bpad + 1 * MLP_LD,
                                    y1, N_EDGES);
    mma_gemm_kernel<<<mgrid, 256>>>(y1, Wpad + 2 * MLP_K * MLP_LD, bpad + 2 * MLP_LD,
                                    y0, N_EDGES);

    out_kernel<<<G((long long)N_EDGES * 32), 256>>>(y0, Wopad, mlp_bo, out);
}